// round 15
// baseline (speedup 1.0000x reference)
#include <cuda_runtime.h>
#include <cuda_bf16.h>
#include <cstdint>

#define NN 100000
#define NE 1600000
#define NG 256
#define DD 128
#define N4 (NN * 32)   // float4 elements per node-feature matrix
#define SCAN_BLK 98    // 98 * 1024 >= NN

// ---------------- scratch (device globals: allocation-free) ----------------
__device__ float4 g_P[N4];       // pooled (agg output, pre-GEMM1)
__device__ float4 g_Z[N4];       // GEMM1 output (pre-BN1)
__device__ float4 g_T[4][N4];    // per-layer GEMM2 output (pre-BN2)
__device__ int    g_counts[NN];
__device__ int    g_rowptr[NN + 1];
__device__ int    g_cursor[NN];
__device__ int    g_csr[NE];
__device__ int    g_bsum[SCAN_BLK];
__device__ int    g_boff[SCAN_BLK];
__device__ float  g_sum[DD];
__device__ float  g_sq[DD];
__device__ float  g_scale[DD];     // current BN (BN1 for gemm2 A-load)
__device__ float  g_shift[DD];
__device__ float  g_scaleL[4][DD]; // saved BN2 per layer
__device__ float  g_shiftL[4][DD];
__device__ float  g_pg[NG * DD];
__device__ int    g_gstart[NG + 1];
__device__ int    g_tick[8];       // per-GEMM-launch last-block tickets

__device__ __forceinline__ uint32_t f2tf32(float v) {
    uint32_t u;
    asm("cvt.rna.tf32.f32 %0, %1;" : "=r"(u) : "f"(v));
    return u;
}
__device__ __forceinline__ void mma_tf32(float* d, const uint32_t* a, const uint32_t* b) {
    asm volatile("mma.sync.aligned.m16n8k8.row.col.f32.tf32.tf32.f32 "
        "{%0,%1,%2,%3}, {%4,%5,%6,%7}, {%8,%9}, {%0,%1,%2,%3};"
        : "+f"(d[0]), "+f"(d[1]), "+f"(d[2]), "+f"(d[3])
        : "r"(a[0]), "r"(a[1]), "r"(a[2]), "r"(a[3]), "r"(b[0]), "r"(b[1]));
}
__device__ __forceinline__ void fuse_acc(float4& acc, float4 t, float4 sc, float4 sh, float wl) {
    acc.x = fmaf(wl, fmaxf(fmaf(t.x, sc.x, sh.x), 0.0f), acc.x);
    acc.y = fmaf(wl, fmaxf(fmaf(t.y, sc.y, sh.y), 0.0f), acc.y);
    acc.z = fmaf(wl, fmaxf(fmaf(t.z, sc.z, sh.z), 0.0f), acc.z);
    acc.w = fmaf(wl, fmaxf(fmaf(t.w, sc.w, sh.w), 0.0f), acc.w);
}

// ---------------- init ----------------
__global__ void k_init() {
    int i = blockIdx.x * blockDim.x + threadIdx.x;
    if (i < NN) g_counts[i] = 0;
    if (i < DD) { g_sum[i] = 0.0f; g_sq[i] = 0.0f; }
    if (i < 8) g_tick[i] = 0;
}

// ---------------- CSR build ----------------
__global__ void k_hist(const int* __restrict__ dst) {
    int i = blockIdx.x * blockDim.x + threadIdx.x;
    if (i < NE) atomicAdd(&g_counts[dst[i]], 1);
}

__device__ __forceinline__ int block_scan_inc(int v, int* sm) {
    int t = threadIdx.x;
    int lane = t & 31;
    int w = t >> 5;
#pragma unroll
    for (int d = 1; d < 32; d <<= 1) {
        int n = __shfl_up_sync(0xffffffffu, v, d);
        if (lane >= d) v += n;
    }
    if (lane == 31) sm[w] = v;
    __syncthreads();
    if (w == 0) {
        int s = (lane < 32) ? sm[lane] : 0;
#pragma unroll
        for (int d = 1; d < 32; d <<= 1) {
            int n = __shfl_up_sync(0xffffffffu, s, d);
            if (lane >= d) s += n;
        }
        sm[lane] = s;
    }
    __syncthreads();
    if (w > 0) v += sm[w - 1];
    return v;
}

__global__ void k_scan1() {
    __shared__ int sm[32];
    int idx = blockIdx.x * 1024 + threadIdx.x;
    int v = (idx < NN) ? g_counts[idx] : 0;
    int inc = block_scan_inc(v, sm);
    if (threadIdx.x == 1023) g_bsum[blockIdx.x] = inc;
}

__global__ void k_scan2() {
    __shared__ int sm[32];
    int t = threadIdx.x;   // 128 threads
    int v = (t < SCAN_BLK) ? g_bsum[t] : 0;
    int lane = t & 31;
    int w = t >> 5;
#pragma unroll
    for (int d = 1; d < 32; d <<= 1) {
        int n = __shfl_up_sync(0xffffffffu, v, d);
        if (lane >= d) v += n;
    }
    if (lane == 31) sm[w] = v;
    __syncthreads();
    if (w == 0) {
        int s = (lane < 4) ? sm[lane] : 0;
#pragma unroll
        for (int d = 1; d < 4; d <<= 1) {
            int n = __shfl_up_sync(0xffffffffu, s, d);
            if (lane >= d) s += n;
        }
        sm[lane] = s;
    }
    __syncthreads();
    if (w > 0) v += sm[w - 1];
    if (t < SCAN_BLK) g_boff[t] = v - g_bsum[t];
    if (t == SCAN_BLK - 1) g_rowptr[NN] = v;
}

__global__ void k_scan3() {
    __shared__ int sm[32];
    int idx = blockIdx.x * 1024 + threadIdx.x;
    int v = (idx < NN) ? g_counts[idx] : 0;
    int inc = block_scan_inc(v, sm);
    int exc = inc - v + g_boff[blockIdx.x];
    if (idx < NN) {
        g_rowptr[idx] = exc;
        g_cursor[idx] = exc;
    }
}

__global__ void k_scatter(const int* __restrict__ src, const int* __restrict__ dst) {
    int i = blockIdx.x * blockDim.x + threadIdx.x;
    if (i < NE) {
        int p = atomicAdd(&g_cursor[dst[i]], 1);
        g_csr[p] = src[i];
    }
}

__global__ void k_gstartk(const int* __restrict__ gid) {
    int i = blockIdx.x * blockDim.x + threadIdx.x;
    if (i >= NN) return;
    int cur = __ldg(&gid[i]);
    int prev = (i == 0) ? -1 : __ldg(&gid[i - 1]);
    for (int g = prev + 1; g <= cur; ++g) g_gstart[g] = i;
    if (i == NN - 1)
        for (int g = cur + 1; g <= NG; ++g) g_gstart[g] = NN;
}

// ------- aggregation: pooled = (1+eps)*f(self) + sum f(neighbors), f = relu(BN) or id ------
__global__ void k_agg(const float4* __restrict__ src, const float* __restrict__ eps,
                      int layer, const float* __restrict__ scl, const float* __restrict__ shl) {
    int gt = blockIdx.x * blockDim.x + threadIdx.x;
    int node = gt >> 5;
    int lane = gt & 31;
    if (node >= NN) return;
    bool bn = layer > 0;
    float4 sc = make_float4(1.0f, 1.0f, 1.0f, 1.0f);
    float4 sh = make_float4(0.0f, 0.0f, 0.0f, 0.0f);
    if (bn) {
        sc = __ldg(&((const float4*)scl)[lane]);
        sh = __ldg(&((const float4*)shl)[lane]);
    }
    float ep = 1.0f + __ldg(&eps[layer]);

#define XF(v) do { if (bn) { \
        v.x = fmaxf(fmaf(v.x, sc.x, sh.x), 0.0f); \
        v.y = fmaxf(fmaf(v.y, sc.y, sh.y), 0.0f); \
        v.z = fmaxf(fmaf(v.z, sc.z, sh.z), 0.0f); \
        v.w = fmaxf(fmaf(v.w, sc.w, sh.w), 0.0f); } } while (0)

    float4 self = src[node * 32 + lane];
    XF(self);
    float4 acc;
    acc.x = ep * self.x; acc.y = ep * self.y; acc.z = ep * self.z; acc.w = ep * self.w;
    int beg = g_rowptr[node];
    int end = g_rowptr[node + 1];
    int e = beg;
    for (; e + 4 <= end; e += 4) {
        int s0 = __ldg(&g_csr[e]);
        int s1 = __ldg(&g_csr[e + 1]);
        int s2 = __ldg(&g_csr[e + 2]);
        int s3 = __ldg(&g_csr[e + 3]);
        float4 v0 = src[s0 * 32 + lane];
        float4 v1 = src[s1 * 32 + lane];
        float4 v2 = src[s2 * 32 + lane];
        float4 v3 = src[s3 * 32 + lane];
        XF(v0); XF(v1); XF(v2); XF(v3);
        acc.x += (v0.x + v1.x) + (v2.x + v3.x);
        acc.y += (v0.y + v1.y) + (v2.y + v3.y);
        acc.z += (v0.z + v1.z) + (v2.z + v3.z);
        acc.w += (v0.w + v1.w) + (v2.w + v3.w);
    }
    for (; e < end; ++e) {
        int s = __ldg(&g_csr[e]);
        float4 v = src[s * 32 + lane];
        XF(v);
        acc.x += v.x; acc.y += v.y; acc.z += v.z; acc.w += v.w;
    }
    g_P[node * 32 + lane] = acc;
#undef XF
}

// ---------- tf32 mma.sync GEMM: 64x64x128 tile/CTA (3 CTA/SM) + last-block BN finalize ----
// grid (rowTiles, 2). mode 0: A raw; mode 1: A = relu(BN(A)) (g_scale/g_shift).
// The grid's LAST block (ticket g_tick[tick_id]) computes scale/shift from the
// accumulated (g_sum, g_sq), saves per-layer copy when slot>=0, and resets stats.
#define LDA 132
#define LDW2 72
#define AS_U32 (64 * LDA)           // 8448
#define WK2_U32 (128 * LDW2)        // 9216
__global__ void __launch_bounds__(256, 3)
k_gemm_mma(const float4* __restrict__ A, float* __restrict__ Yf,
           const float* __restrict__ W, const float* __restrict__ bias, int mode, int M,
           const float* __restrict__ gamma, const float* __restrict__ beta,
           int slot, int tick_id) {
    extern __shared__ uint32_t smem[];
    uint32_t* As = smem;                            // 8448 u32
    uint32_t* Wk = smem + AS_U32;                   // 9216 u32
    float* sS = (float*)(smem + AS_U32 + WK2_U32);  // 64
    float* sQ = sS + 64;                            // 64

    int tid = threadIdx.x;
    int lane = tid & 31;
    int wid = tid >> 5;
    int wm = wid & 1;       // warp row (2 x 32 rows)
    int wn = wid >> 1;      // warp col (4 x 16 cols)
    int gr = lane >> 2;     // group row 0..7
    int tg = lane & 3;      // thread-in-group 0..3

    const float4* sc4 = (const float4*)g_scale;
    const float4* sh4 = (const float4*)g_shift;
    int rowBase = blockIdx.x * 64;
    int nBase = blockIdx.y * 64;

    if (tid < 64) { sS[tid] = 0.0f; sQ[tid] = 0.0f; }

    // stage W half K-major: Wk[k][n'] = W[k*128 + nBase + n'], n' in [0,64)
    {
        const float4* W4 = (const float4*)W;
        int nb4 = nBase >> 2;
        for (int j = tid; j < 2048; j += 256) {
            int k = j >> 4;
            int n4 = j & 15;
            float4 w = __ldg(&W4[k * 32 + nb4 + n4]);
            uint4 u;
            u.x = f2tf32(w.x); u.y = f2tf32(w.y); u.z = f2tf32(w.z); u.w = f2tf32(w.w);
            *(uint4*)&Wk[k * LDW2 + n4 * 4] = u;
        }
    }

    // stage A tile (64 rows), tf32-converted, optional BN+ReLU
    for (int j = tid; j < 2048; j += 256) {
        int r = j >> 5;
        int q = j & 31;
        int row = rowBase + r;
        float4 v = make_float4(0.0f, 0.0f, 0.0f, 0.0f);
        if (row < M) {
            v = A[row * 32 + q];
            if (mode) {
                float4 sc = sc4[q];
                float4 sh = sh4[q];
                v.x = fmaxf(fmaf(v.x, sc.x, sh.x), 0.0f);
                v.y = fmaxf(fmaf(v.y, sc.y, sh.y), 0.0f);
                v.z = fmaxf(fmaf(v.z, sc.z, sh.z), 0.0f);
                v.w = fmaxf(fmaf(v.w, sc.w, sh.w), 0.0f);
            }
        }
        uint4 u;
        u.x = f2tf32(v.x); u.y = f2tf32(v.y); u.z = f2tf32(v.z); u.w = f2tf32(v.w);
        *(uint4*)&As[r * LDA + q * 4] = u;
    }
    __syncthreads();

    // mainloop: warp tile 32 (m) x 16 (n)
    float C[2][2][4];
#pragma unroll
    for (int m = 0; m < 2; ++m)
#pragma unroll
        for (int t = 0; t < 2; ++t)
#pragma unroll
            for (int c = 0; c < 4; ++c) C[m][t][c] = 0.0f;

    const uint32_t* Asw = As + (wm * 32 + gr) * LDA + tg;
    const uint32_t* Wkw = Wk + tg * LDW2 + (wn * 16 + gr);

#pragma unroll
    for (int ks = 0; ks < 128; ks += 8) {
        uint32_t a[2][4];
#pragma unroll
        for (int m = 0; m < 2; ++m) {
            const uint32_t* p = Asw + m * 16 * LDA + ks;
            a[m][0] = p[0];
            a[m][1] = p[8 * LDA];
            a[m][2] = p[4];
            a[m][3] = p[8 * LDA + 4];
        }
        const uint32_t* qb = Wkw + ks * LDW2;
#pragma unroll
        for (int t = 0; t < 2; ++t) {
            uint32_t b[2];
            b[0] = qb[t * 8];
            b[1] = qb[4 * LDW2 + t * 8];
            mma_tf32(C[0][t], a[0], b);
            mma_tf32(C[1][t], a[1], b);
        }
    }

    // epilogue: bias, store, per-column sum/sumsq (local 64-col stats)
#pragma unroll
    for (int t = 0; t < 2; ++t) {
        int colL = wn * 16 + t * 8 + tg * 2;
        int col0 = nBase + colL;
        float b0 = __ldg(&bias[col0]);
        float b1 = __ldg(&bias[col0 + 1]);
        float s0 = 0.0f, s1 = 0.0f, q0 = 0.0f, q1 = 0.0f;
#pragma unroll
        for (int m = 0; m < 2; ++m) {
            int r0 = rowBase + wm * 32 + m * 16 + gr;
            if (r0 < M) {
                float o0 = C[m][t][0] + b0;
                float o1 = C[m][t][1] + b1;
                *(float2*)&Yf[r0 * 128 + col0] = make_float2(o0, o1);
                s0 += o0; q0 += o0 * o0;
                s1 += o1; q1 += o1 * o1;
            }
            int r1 = r0 + 8;
            if (r1 < M) {
                float o2 = C[m][t][2] + b0;
                float o3 = C[m][t][3] + b1;
                *(float2*)&Yf[r1 * 128 + col0] = make_float2(o2, o3);
                s0 += o2; q0 += o2 * o2;
                s1 += o3; q1 += o3 * o3;
            }
        }
#pragma unroll
        for (int d = 4; d < 32; d <<= 1) {
            s0 += __shfl_xor_sync(0xffffffffu, s0, d);
            s1 += __shfl_xor_sync(0xffffffffu, s1, d);
            q0 += __shfl_xor_sync(0xffffffffu, q0, d);
            q1 += __shfl_xor_sync(0xffffffffu, q1, d);
        }
        if (gr == 0) {
            atomicAdd(&sS[colL], s0);
            atomicAdd(&sS[colL + 1], s1);
            atomicAdd(&sQ[colL], q0);
            atomicAdd(&sQ[colL + 1], q1);
        }
    }
    __syncthreads();
    if (tid < 64) {
        atomicAdd(&g_sum[nBase + tid], sS[tid]);
        atomicAdd(&g_sq[nBase + tid], sQ[tid]);
    }

    // ---- last-block BN finalize ----
    __shared__ int s_last;
    __threadfence();
    __syncthreads();
    if (tid == 0) {
        int total = gridDim.x * gridDim.y;
        s_last = (atomicAdd(&g_tick[tick_id], 1) == total - 1) ? 1 : 0;
    }
    __syncthreads();
    if (s_last && tid < DD) {
        float m = g_sum[tid] * (1.0f / NN);
        float q = g_sq[tid] * (1.0f / NN);
        float var = q - m * m;
        float rstd = rsqrtf(var + 1e-5f);
        float sc = rstd * __ldg(&gamma[tid]);
        float sh = fmaf(-m, sc, __ldg(&beta[tid]));
        g_scale[tid] = sc;
        g_shift[tid] = sh;
        if (slot >= 0) { g_scaleL[slot][tid] = sc; g_shiftL[slot][tid] = sh; }
        g_sum[tid] = 0.0f;
        g_sq[tid] = 0.0f;
    }
}

// --------- fuse+pool: per graph, sum_l w_l * relu(BN_l(T_l)) summed over nodes --------
__global__ void __launch_bounds__(512)
k_fusepool(const float* __restrict__ fw) {
    __shared__ float4 red[512];
    int g = blockIdx.x;
    int tid = threadIdx.x;
    int c4 = tid & 31;
    int sr = tid >> 5;   // 16 subrows
    float w0 = __ldg(&fw[0]), w1 = __ldg(&fw[1]), w2 = __ldg(&fw[2]), w3 = __ldg(&fw[3]);
    float4 sc0 = __ldg(&((const float4*)g_scaleL[0])[c4]);
    float4 sh0 = __ldg(&((const float4*)g_shiftL[0])[c4]);
    float4 sc1 = __ldg(&((const float4*)g_scaleL[1])[c4]);
    float4 sh1 = __ldg(&((const float4*)g_shiftL[1])[c4]);
    float4 sc2 = __ldg(&((const float4*)g_scaleL[2])[c4]);
    float4 sh2 = __ldg(&((const float4*)g_shiftL[2])[c4]);
    float4 sc3 = __ldg(&((const float4*)g_scaleL[3])[c4]);
    float4 sh3 = __ldg(&((const float4*)g_shiftL[3])[c4]);
    float4 acc = make_float4(0.0f, 0.0f, 0.0f, 0.0f);
    int beg = g_gstart[g];
    int end = g_gstart[g + 1];
    for (int n = beg + sr; n < end; n += 16) {
        int idx = n * 32 + c4;
        fuse_acc(acc, g_T[0][idx], sc0, sh0, w0);
        fuse_acc(acc, g_T[1][idx], sc1, sh1, w1);
        fuse_acc(acc, g_T[2][idx], sc2, sh2, w2);
        fuse_acc(acc, g_T[3][idx], sc3, sh3, w3);
    }
    red[tid] = acc;
    __syncthreads();
    if (sr < 4) {
        float4 a = red[sr * 32 + c4];
#pragma unroll
        for (int s = 4; s < 16; s += 4) {
            float4 b = red[(sr + s) * 32 + c4];
            a.x += b.x; a.y += b.y; a.z += b.z; a.w += b.w;
        }
        red[sr * 32 + c4] = a;
    }
    __syncthreads();
    if (sr == 0) {
        float4 a = red[c4];
#pragma unroll
        for (int s = 1; s < 4; ++s) {
            float4 b = red[s * 32 + c4];
            a.x += b.x; a.y += b.y; a.z += b.z; a.w += b.w;
        }
        ((float4*)g_pg)[g * 32 + c4] = a;
    }
}

// ---------------- final linear 128 -> 10 ----------------
__global__ void k_out(const float* __restrict__ Wp, const float* __restrict__ bp,
                      float* __restrict__ out) {
    int g = blockIdx.x;
    int lane = threadIdx.x;
    float acc[10];
#pragma unroll
    for (int j = 0; j < 10; ++j) acc[j] = 0.0f;
    for (int k = lane; k < DD; k += 32) {
        float pv = g_pg[g * DD + k];
#pragma unroll
        for (int j = 0; j < 10; ++j) acc[j] += pv * __ldg(&Wp[k * 10 + j]);
    }
#pragma unroll
    for (int j = 0; j < 10; ++j) {
        float v = acc[j];
        v += __shfl_xor_sync(0xffffffffu, v, 16);
        v += __shfl_xor_sync(0xffffffffu, v, 8);
        v += __shfl_xor_sync(0xffffffffu, v, 4);
        v += __shfl_xor_sync(0xffffffffu, v, 2);
        v += __shfl_xor_sync(0xffffffffu, v, 1);
        if (lane == 0) out[g * 10 + j] = v + __ldg(&bp[j]);
    }
}

// ---------------- launch ----------------
extern "C" void kernel_launch(void* const* d_in, const int* in_sizes, int n_in,
                              void* d_out, int out_size) {
    const float4* x   = (const float4*)d_in[0];
    const int* esrc   = (const int*)d_in[1];
    const int* edst   = (const int*)d_in[2];
    const int* gid    = (const int*)d_in[3];
    const float* eps  = (const float*)d_in[4];
    const float* fw   = (const float*)d_in[5];
    const float* W1   = (const float*)d_in[6];
    const float* b1   = (const float*)d_in[7];
    const float* g1   = (const float*)d_in[8];
    const float* bt1  = (const float*)d_in[9];
    const float* W2   = (const float*)d_in[10];
    const float* b2   = (const float*)d_in[11];
    const float* g2   = (const float*)d_in[12];
    const float* bt2  = (const float*)d_in[13];
    const float* Wp   = (const float*)d_in[14];
    const float* bp   = (const float*)d_in[15];
    float* out        = (float*)d_out;

    const int SMEM_GEMM = (AS_U32 + WK2_U32 + 128) * 4;   // 71168 bytes -> 3 CTA/SM
    cudaFuncSetAttribute(k_gemm_mma, cudaFuncAttributeMaxDynamicSharedMemorySize, SMEM_GEMM);

    k_init<<<(NN + 255) / 256, 256>>>();
    k_hist<<<(NE + 255) / 256, 256>>>(edst);
    k_scan1<<<SCAN_BLK, 1024>>>();
    k_scan2<<<1, 128>>>();
    k_scan3<<<SCAN_BLK, 1024>>>();
    k_scatter<<<(NE + 255) / 256, 256>>>(esrc, edst);
    k_gstartk<<<(NN + 255) / 256, 256>>>(gid);

    const int AGG_BLOCKS = (NN * 32 + 255) / 256;   // 12500
    const int ROW_TILES = (NN + 63) / 64;           // 1563
    dim3 gemm_grid(ROW_TILES, 2);

    // device pointers into device globals
    float4* Tl[4];
    cudaGetSymbolAddress((void**)&Tl[0], g_T);
    Tl[1] = Tl[0] + N4;
    Tl[2] = Tl[0] + 2 * N4;
    Tl[3] = Tl[0] + 3 * N4;
    float4* Pp; cudaGetSymbolAddress((void**)&Pp, g_P);
    float4* Zp; cudaGetSymbolAddress((void**)&Zp, g_Z);
    float* scL; cudaGetSymbolAddress((void**)&scL, g_scaleL);
    float* shL; cudaGetSymbolAddress((void**)&shL, g_shiftL);

    for (int l = 0; l < 4; ++l) {
        const float4* src = (l == 0) ? x : (const float4*)Tl[l - 1];
        k_agg<<<AGG_BLOCKS, 256>>>(src, eps, l,
                                   scL + (l > 0 ? (l - 1) * DD : 0),
                                   shL + (l > 0 ? (l - 1) * DD : 0));
        k_gemm_mma<<<gemm_grid, 256, SMEM_GEMM>>>(Pp, (float*)Zp,
                                                  W1 + l * 16384, b1 + l * 128, 0, NN,
                                                  g1 + l * DD, bt1 + l * DD, -1, l * 2);
        k_gemm_mma<<<gemm_grid, 256, SMEM_GEMM>>>(Zp, (float*)Tl[l],
                                                  W2 + l * 16384, b2 + l * 128, 1, NN,
                                                  g2 + l * DD, bt2 + l * DD, l, l * 2 + 1);
    }
    k_fusepool<<<NG, 512>>>(fw);
    k_out<<<NG, 32>>>(Wp, bp, out);
}

// round 16
// speedup vs baseline: 1.0261x; 1.0261x over previous
#include <cuda_runtime.h>
#include <cuda_bf16.h>
#include <cstdint>

#define NN 100000
#define NE 1600000
#define NG 256
#define DD 128
#define N4 (NN * 32)   // float4 elements per node-feature matrix (= uint2-bf16 count)
#define SCAN_BLK 98    // 98 * 1024 >= NN

// ---------------- scratch (device globals: allocation-free) ----------------
__device__ float4 g_P[N4];       // pooled (agg output, pre-GEMM1)
__device__ float4 g_Z[N4];       // GEMM1 output (pre-BN1)
__device__ float4 g_T[4][N4];    // per-layer GEMM2 output fp32 (for fusepool)
__device__ uint2  g_Tb[4][N4];   // per-layer GEMM2 output bf16 (for gather)
__device__ uint2  g_xb[N4];      // bf16 copy of x (for layer-0 gather)
__device__ int    g_counts[NN];
__device__ int    g_rowptr[NN + 1];
__device__ int    g_cursor[NN];
__device__ int    g_csr[NE];
__device__ int    g_bsum[SCAN_BLK];
__device__ int    g_boff[SCAN_BLK];
__device__ float  g_sum[DD];
__device__ float  g_sq[DD];
__device__ float  g_scale[DD];     // current BN (BN1 for gemm2 A-load)
__device__ float  g_shift[DD];
__device__ float  g_scaleL[4][DD]; // saved BN2 per layer
__device__ float  g_shiftL[4][DD];
__device__ float  g_pg[NG * DD];
__device__ int    g_gstart[NG + 1];

__device__ __forceinline__ uint32_t f2tf32(float v) {
    uint32_t u;
    asm("cvt.rna.tf32.f32 %0, %1;" : "=r"(u) : "f"(v));
    return u;
}
__device__ __forceinline__ void mma_tf32(float* d, const uint32_t* a, const uint32_t* b) {
    asm volatile("mma.sync.aligned.m16n8k8.row.col.f32.tf32.tf32.f32 "
        "{%0,%1,%2,%3}, {%4,%5,%6,%7}, {%8,%9}, {%0,%1,%2,%3};"
        : "+f"(d[0]), "+f"(d[1]), "+f"(d[2]), "+f"(d[3])
        : "r"(a[0]), "r"(a[1]), "r"(a[2]), "r"(a[3]), "r"(b[0]), "r"(b[1]));
}
__device__ __forceinline__ void fuse_acc(float4& acc, float4 t, float4 sc, float4 sh, float wl) {
    acc.x = fmaf(wl, fmaxf(fmaf(t.x, sc.x, sh.x), 0.0f), acc.x);
    acc.y = fmaf(wl, fmaxf(fmaf(t.y, sc.y, sh.y), 0.0f), acc.y);
    acc.z = fmaf(wl, fmaxf(fmaf(t.z, sc.z, sh.z), 0.0f), acc.z);
    acc.w = fmaf(wl, fmaxf(fmaf(t.w, sc.w, sh.w), 0.0f), acc.w);
}
// bf16x2-pair (uint2) -> float4 via pure bit ops (bf16->f32 is a 16-bit shift)
__device__ __forceinline__ float4 bf2f4(uint2 u) {
    float4 f;
    f.x = __uint_as_float(u.x << 16);
    f.y = __uint_as_float(u.x & 0xffff0000u);
    f.z = __uint_as_float(u.y << 16);
    f.w = __uint_as_float(u.y & 0xffff0000u);
    return f;
}

// ---------------- init ----------------
__global__ void k_init() {
    int i = blockIdx.x * blockDim.x + threadIdx.x;
    if (i < NN) g_counts[i] = 0;
    if (i < DD) { g_sum[i] = 0.0f; g_sq[i] = 0.0f; }
}

// ---------------- x -> bf16 ----------------
__global__ void k_cvt(const float4* __restrict__ x) {
    int i = blockIdx.x * blockDim.x + threadIdx.x;
    if (i >= N4) return;
    float4 v = x[i];
    __nv_bfloat162 p0 = __float22bfloat162_rn(make_float2(v.x, v.y));
    __nv_bfloat162 p1 = __float22bfloat162_rn(make_float2(v.z, v.w));
    uint2 u;
    u.x = *reinterpret_cast<uint32_t*>(&p0);
    u.y = *reinterpret_cast<uint32_t*>(&p1);
    g_xb[i] = u;
}

// ---------------- CSR build ----------------
__global__ void k_hist(const int* __restrict__ dst) {
    int i = blockIdx.x * blockDim.x + threadIdx.x;
    if (i < NE) atomicAdd(&g_counts[dst[i]], 1);
}

__device__ __forceinline__ int block_scan_inc(int v, int* sm) {
    int t = threadIdx.x;
    int lane = t & 31;
    int w = t >> 5;
#pragma unroll
    for (int d = 1; d < 32; d <<= 1) {
        int n = __shfl_up_sync(0xffffffffu, v, d);
        if (lane >= d) v += n;
    }
    if (lane == 31) sm[w] = v;
    __syncthreads();
    if (w == 0) {
        int s = (lane < 32) ? sm[lane] : 0;
#pragma unroll
        for (int d = 1; d < 32; d <<= 1) {
            int n = __shfl_up_sync(0xffffffffu, s, d);
            if (lane >= d) s += n;
        }
        sm[lane] = s;
    }
    __syncthreads();
    if (w > 0) v += sm[w - 1];
    return v;
}

__global__ void k_scan1() {
    __shared__ int sm[32];
    int idx = blockIdx.x * 1024 + threadIdx.x;
    int v = (idx < NN) ? g_counts[idx] : 0;
    int inc = block_scan_inc(v, sm);
    if (threadIdx.x == 1023) g_bsum[blockIdx.x] = inc;
}

__global__ void k_scan2() {
    __shared__ int sm[32];
    int t = threadIdx.x;   // 128 threads
    int v = (t < SCAN_BLK) ? g_bsum[t] : 0;
    int lane = t & 31;
    int w = t >> 5;
#pragma unroll
    for (int d = 1; d < 32; d <<= 1) {
        int n = __shfl_up_sync(0xffffffffu, v, d);
        if (lane >= d) v += n;
    }
    if (lane == 31) sm[w] = v;
    __syncthreads();
    if (w == 0) {
        int s = (lane < 4) ? sm[lane] : 0;
#pragma unroll
        for (int d = 1; d < 4; d <<= 1) {
            int n = __shfl_up_sync(0xffffffffu, s, d);
            if (lane >= d) s += n;
        }
        sm[lane] = s;
    }
    __syncthreads();
    if (w > 0) v += sm[w - 1];
    if (t < SCAN_BLK) g_boff[t] = v - g_bsum[t];
    if (t == SCAN_BLK - 1) g_rowptr[NN] = v;
}

__global__ void k_scan3() {
    __shared__ int sm[32];
    int idx = blockIdx.x * 1024 + threadIdx.x;
    int v = (idx < NN) ? g_counts[idx] : 0;
    int inc = block_scan_inc(v, sm);
    int exc = inc - v + g_boff[blockIdx.x];
    if (idx < NN) {
        g_rowptr[idx] = exc;
        g_cursor[idx] = exc;
    }
}

__global__ void k_scatter(const int* __restrict__ src, const int* __restrict__ dst) {
    int i = blockIdx.x * blockDim.x + threadIdx.x;
    if (i < NE) {
        int p = atomicAdd(&g_cursor[dst[i]], 1);
        g_csr[p] = src[i];
    }
}

__global__ void k_gstartk(const int* __restrict__ gid) {
    int i = blockIdx.x * blockDim.x + threadIdx.x;
    if (i >= NN) return;
    int cur = __ldg(&gid[i]);
    int prev = (i == 0) ? -1 : __ldg(&gid[i - 1]);
    for (int g = prev + 1; g <= cur; ++g) g_gstart[g] = i;
    if (i == NN - 1)
        for (int g = cur + 1; g <= NG; ++g) g_gstart[g] = NN;
}

// --- aggregation (bf16 src): pooled = (1+eps)*f(self) + sum f(nb), f = relu(BN) or id ---
__global__ void k_agg(const uint2* __restrict__ src, const float* __restrict__ eps,
                      int layer, const float* __restrict__ scl, const float* __restrict__ shl) {
    int gt = blockIdx.x * blockDim.x + threadIdx.x;
    int node = gt >> 5;
    int lane = gt & 31;
    if (node >= NN) return;
    bool bn = layer > 0;
    float4 sc = make_float4(1.0f, 1.0f, 1.0f, 1.0f);
    float4 sh = make_float4(0.0f, 0.0f, 0.0f, 0.0f);
    if (bn) {
        sc = __ldg(&((const float4*)scl)[lane]);
        sh = __ldg(&((const float4*)shl)[lane]);
    }
    float ep = 1.0f + __ldg(&eps[layer]);

#define XF(v) do { if (bn) { \
        v.x = fmaxf(fmaf(v.x, sc.x, sh.x), 0.0f); \
        v.y = fmaxf(fmaf(v.y, sc.y, sh.y), 0.0f); \
        v.z = fmaxf(fmaf(v.z, sc.z, sh.z), 0.0f); \
        v.w = fmaxf(fmaf(v.w, sc.w, sh.w), 0.0f); } } while (0)

    float4 self = bf2f4(__ldg(&src[node * 32 + lane]));
    XF(self);
    float4 acc;
    acc.x = ep * self.x; acc.y = ep * self.y; acc.z = ep * self.z; acc.w = ep * self.w;
    int beg = g_rowptr[node];
    int end = g_rowptr[node + 1];
    int e = beg;
    for (; e + 4 <= end; e += 4) {
        int s0 = __ldg(&g_csr[e]);
        int s1 = __ldg(&g_csr[e + 1]);
        int s2 = __ldg(&g_csr[e + 2]);
        int s3 = __ldg(&g_csr[e + 3]);
        float4 v0 = bf2f4(__ldg(&src[s0 * 32 + lane]));
        float4 v1 = bf2f4(__ldg(&src[s1 * 32 + lane]));
        float4 v2 = bf2f4(__ldg(&src[s2 * 32 + lane]));
        float4 v3 = bf2f4(__ldg(&src[s3 * 32 + lane]));
        XF(v0); XF(v1); XF(v2); XF(v3);
        acc.x += (v0.x + v1.x) + (v2.x + v3.x);
        acc.y += (v0.y + v1.y) + (v2.y + v3.y);
        acc.z += (v0.z + v1.z) + (v2.z + v3.z);
        acc.w += (v0.w + v1.w) + (v2.w + v3.w);
    }
    for (; e < end; ++e) {
        int s = __ldg(&g_csr[e]);
        float4 v = bf2f4(__ldg(&src[s * 32 + lane]));
        XF(v);
        acc.x += v.x; acc.y += v.y; acc.z += v.z; acc.w += v.w;
    }
    g_P[node * 32 + lane] = acc;
#undef XF
}

// ---------- tf32 mma.sync GEMM: 64x64x128 tile/CTA (3 CTA/SM), fused bias + BN stats -----
// grid (rowTiles, 2): blockIdx.y selects the 64-column half of W.
// mode 0: A raw; mode 1: A = relu(BN(A)) on the fly (g_scale/g_shift)
// Yb != nullptr: additionally write packed-bf16 copy of output (row stride 64 u32)
#define LDA 132
#define LDW2 72
#define AS_U32 (64 * LDA)           // 8448
#define WK2_U32 (128 * LDW2)        // 9216
__global__ void __launch_bounds__(256, 3)
k_gemm_mma(const float4* __restrict__ A, float* __restrict__ Yf, uint32_t* __restrict__ Yb,
           const float* __restrict__ W, const float* __restrict__ bias, int mode, int M) {
    extern __shared__ uint32_t smem[];
    uint32_t* As = smem;                            // 8448 u32
    uint32_t* Wk = smem + AS_U32;                   // 9216 u32
    float* sS = (float*)(smem + AS_U32 + WK2_U32);  // 64
    float* sQ = sS + 64;                            // 64

    int tid = threadIdx.x;
    int lane = tid & 31;
    int wid = tid >> 5;
    int wm = wid & 1;       // warp row (2 x 32 rows)
    int wn = wid >> 1;      // warp col (4 x 16 cols)
    int gr = lane >> 2;     // group row 0..7
    int tg = lane & 3;      // thread-in-group 0..3

    const float4* sc4 = (const float4*)g_scale;
    const float4* sh4 = (const float4*)g_shift;
    int rowBase = blockIdx.x * 64;
    int nBase = blockIdx.y * 64;

    if (tid < 64) { sS[tid] = 0.0f; sQ[tid] = 0.0f; }

    // stage W half K-major: Wk[k][n'] = W[k*128 + nBase + n'], n' in [0,64)
    {
        const float4* W4 = (const float4*)W;
        int nb4 = nBase >> 2;
        for (int j = tid; j < 2048; j += 256) {
            int k = j >> 4;
            int n4 = j & 15;
            float4 w = __ldg(&W4[k * 32 + nb4 + n4]);
            uint4 u;
            u.x = f2tf32(w.x); u.y = f2tf32(w.y); u.z = f2tf32(w.z); u.w = f2tf32(w.w);
            *(uint4*)&Wk[k * LDW2 + n4 * 4] = u;
        }
    }

    // stage A tile (64 rows), tf32-converted, optional BN+ReLU
    for (int j = tid; j < 2048; j += 256) {
        int r = j >> 5;
        int q = j & 31;
        int row = rowBase + r;
        float4 v = make_float4(0.0f, 0.0f, 0.0f, 0.0f);
        if (row < M) {
            v = A[row * 32 + q];
            if (mode) {
                float4 sc = sc4[q];
                float4 sh = sh4[q];
                v.x = fmaxf(fmaf(v.x, sc.x, sh.x), 0.0f);
                v.y = fmaxf(fmaf(v.y, sc.y, sh.y), 0.0f);
                v.z = fmaxf(fmaf(v.z, sc.z, sh.z), 0.0f);
                v.w = fmaxf(fmaf(v.w, sc.w, sh.w), 0.0f);
            }
        }
        uint4 u;
        u.x = f2tf32(v.x); u.y = f2tf32(v.y); u.z = f2tf32(v.z); u.w = f2tf32(v.w);
        *(uint4*)&As[r * LDA + q * 4] = u;
    }
    __syncthreads();

    // mainloop: warp tile 32 (m) x 16 (n)
    float C[2][2][4];
#pragma unroll
    for (int m = 0; m < 2; ++m)
#pragma unroll
        for (int t = 0; t < 2; ++t)
#pragma unroll
            for (int c = 0; c < 4; ++c) C[m][t][c] = 0.0f;

    const uint32_t* Asw = As + (wm * 32 + gr) * LDA + tg;
    const uint32_t* Wkw = Wk + tg * LDW2 + (wn * 16 + gr);

#pragma unroll
    for (int ks = 0; ks < 128; ks += 8) {
        uint32_t a[2][4];
#pragma unroll
        for (int m = 0; m < 2; ++m) {
            const uint32_t* p = Asw + m * 16 * LDA + ks;
            a[m][0] = p[0];
            a[m][1] = p[8 * LDA];
            a[m][2] = p[4];
            a[m][3] = p[8 * LDA + 4];
        }
        const uint32_t* qb = Wkw + ks * LDW2;
#pragma unroll
        for (int t = 0; t < 2; ++t) {
            uint32_t b[2];
            b[0] = qb[t * 8];
            b[1] = qb[4 * LDW2 + t * 8];
            mma_tf32(C[0][t], a[0], b);
            mma_tf32(C[1][t], a[1], b);
        }
    }

    // epilogue: bias, store (fp32 + optional bf16), per-column sum/sumsq (local 64 cols)
#pragma unroll
    for (int t = 0; t < 2; ++t) {
        int colL = wn * 16 + t * 8 + tg * 2;
        int col0 = nBase + colL;
        float b0 = __ldg(&bias[col0]);
        float b1 = __ldg(&bias[col0 + 1]);
        float s0 = 0.0f, s1 = 0.0f, q0 = 0.0f, q1 = 0.0f;
#pragma unroll
        for (int m = 0; m < 2; ++m) {
            int r0 = rowBase + wm * 32 + m * 16 + gr;
            if (r0 < M) {
                float o0 = C[m][t][0] + b0;
                float o1 = C[m][t][1] + b1;
                *(float2*)&Yf[r0 * 128 + col0] = make_float2(o0, o1);
                if (Yb) {
                    __nv_bfloat162 pb = __float22bfloat162_rn(make_float2(o0, o1));
                    Yb[r0 * 64 + (col0 >> 1)] = *reinterpret_cast<uint32_t*>(&pb);
                }
                s0 += o0; q0 += o0 * o0;
                s1 += o1; q1 += o1 * o1;
            }
            int r1 = r0 + 8;
            if (r1 < M) {
                float o2 = C[m][t][2] + b0;
                float o3 = C[m][t][3] + b1;
                *(float2*)&Yf[r1 * 128 + col0] = make_float2(o2, o3);
                if (Yb) {
                    __nv_bfloat162 pb = __float22bfloat162_rn(make_float2(o2, o3));
                    Yb[r1 * 64 + (col0 >> 1)] = *reinterpret_cast<uint32_t*>(&pb);
                }
                s0 += o2; q0 += o2 * o2;
                s1 += o3; q1 += o3 * o3;
            }
        }
#pragma unroll
        for (int d = 4; d < 32; d <<= 1) {
            s0 += __shfl_xor_sync(0xffffffffu, s0, d);
            s1 += __shfl_xor_sync(0xffffffffu, s1, d);
            q0 += __shfl_xor_sync(0xffffffffu, q0, d);
            q1 += __shfl_xor_sync(0xffffffffu, q1, d);
        }
        if (gr == 0) {
            atomicAdd(&sS[colL], s0);
            atomicAdd(&sS[colL + 1], s1);
            atomicAdd(&sQ[colL], q0);
            atomicAdd(&sQ[colL + 1], q1);
        }
    }
    __syncthreads();
    if (tid < 64) {
        atomicAdd(&g_sum[nBase + tid], sS[tid]);
        atomicAdd(&g_sq[nBase + tid], sQ[tid]);
    }
}

// ---------------- BN finalize: (sum,sumsq)->(scale,shift), save per-layer, reset ----------
__global__ void k_finalize(const float* __restrict__ gamma, const float* __restrict__ beta,
                           int slot) {
    int t = threadIdx.x;
    float m = g_sum[t] * (1.0f / NN);
    float q = g_sq[t] * (1.0f / NN);
    float var = q - m * m;
    float rstd = rsqrtf(var + 1e-5f);
    float sc = rstd * __ldg(&gamma[t]);
    float sh = fmaf(-m, sc, __ldg(&beta[t]));
    g_scale[t] = sc;
    g_shift[t] = sh;
    if (slot >= 0) { g_scaleL[slot][t] = sc; g_shiftL[slot][t] = sh; }
    g_sum[t] = 0.0f;
    g_sq[t] = 0.0f;
}

// --------- fuse+pool: per graph, sum_l w_l * relu(BN_l(T_l)) summed over nodes --------
__global__ void __launch_bounds__(512)
k_fusepool(const float* __restrict__ fw) {
    __shared__ float4 red[512];
    int g = blockIdx.x;
    int tid = threadIdx.x;
    int c4 = tid & 31;
    int sr = tid >> 5;   // 16 subrows
    float w0 = __ldg(&fw[0]), w1 = __ldg(&fw[1]), w2 = __ldg(&fw[2]), w3 = __ldg(&fw[3]);
    float4 sc0 = __ldg(&((const float4*)g_scaleL[0])[c4]);
    float4 sh0 = __ldg(&((const float4*)g_shiftL[0])[c4]);
    float4 sc1 = __ldg(&((const float4*)g_scaleL[1])[c4]);
    float4 sh1 = __ldg(&((const float4*)g_shiftL[1])[c4]);
    float4 sc2 = __ldg(&((const float4*)g_scaleL[2])[c4]);
    float4 sh2 = __ldg(&((const float4*)g_shiftL[2])[c4]);
    float4 sc3 = __ldg(&((const float4*)g_scaleL[3])[c4]);
    float4 sh3 = __ldg(&((const float4*)g_shiftL[3])[c4]);
    float4 acc = make_float4(0.0f, 0.0f, 0.0f, 0.0f);
    int beg = g_gstart[g];
    int end = g_gstart[g + 1];
    for (int n = beg + sr; n < end; n += 16) {
        int idx = n * 32 + c4;
        fuse_acc(acc, g_T[0][idx], sc0, sh0, w0);
        fuse_acc(acc, g_T[1][idx], sc1, sh1, w1);
        fuse_acc(acc, g_T[2][idx], sc2, sh2, w2);
        fuse_acc(acc, g_T[3][idx], sc3, sh3, w3);
    }
    red[tid] = acc;
    __syncthreads();
    if (sr < 4) {
        float4 a = red[sr * 32 + c4];
#pragma unroll
        for (int s = 4; s < 16; s += 4) {
            float4 b = red[(sr + s) * 32 + c4];
            a.x += b.x; a.y += b.y; a.z += b.z; a.w += b.w;
        }
        red[sr * 32 + c4] = a;
    }
    __syncthreads();
    if (sr == 0) {
        float4 a = red[c4];
#pragma unroll
        for (int s = 1; s < 4; ++s) {
            float4 b = red[s * 32 + c4];
            a.x += b.x; a.y += b.y; a.z += b.z; a.w += b.w;
        }
        ((float4*)g_pg)[g * 32 + c4] = a;
    }
}

// ---------------- final linear 128 -> 10 ----------------
__global__ void k_out(const float* __restrict__ Wp, const float* __restrict__ bp,
                      float* __restrict__ out) {
    int g = blockIdx.x;
    int lane = threadIdx.x;
    float acc[10];
#pragma unroll
    for (int j = 0; j < 10; ++j) acc[j] = 0.0f;
    for (int k = lane; k < DD; k += 32) {
        float pv = g_pg[g * DD + k];
#pragma unroll
        for (int j = 0; j < 10; ++j) acc[j] += pv * __ldg(&Wp[k * 10 + j]);
    }
#pragma unroll
    for (int j = 0; j < 10; ++j) {
        float v = acc[j];
        v += __shfl_xor_sync(0xffffffffu, v, 16);
        v += __shfl_xor_sync(0xffffffffu, v, 8);
        v += __shfl_xor_sync(0xffffffffu, v, 4);
        v += __shfl_xor_sync(0xffffffffu, v, 2);
        v += __shfl_xor_sync(0xffffffffu, v, 1);
        if (lane == 0) out[g * 10 + j] = v + __ldg(&bp[j]);
    }
}

// ---------------- launch ----------------
extern "C" void kernel_launch(void* const* d_in, const int* in_sizes, int n_in,
                              void* d_out, int out_size) {
    const float4* x   = (const float4*)d_in[0];
    const int* esrc   = (const int*)d_in[1];
    const int* edst   = (const int*)d_in[2];
    const int* gid    = (const int*)d_in[3];
    const float* eps  = (const float*)d_in[4];
    const float* fw   = (const float*)d_in[5];
    const float* W1   = (const float*)d_in[6];
    const float* b1   = (const float*)d_in[7];
    const float* g1   = (const float*)d_in[8];
    const float* bt1  = (const float*)d_in[9];
    const float* W2   = (const float*)d_in[10];
    const float* b2   = (const float*)d_in[11];
    const float* g2   = (const float*)d_in[12];
    const float* bt2  = (const float*)d_in[13];
    const float* Wp   = (const float*)d_in[14];
    const float* bp   = (const float*)d_in[15];
    float* out        = (float*)d_out;

    const int SMEM_GEMM = (AS_U32 + WK2_U32 + 128) * 4;   // 71168 bytes -> 3 CTA/SM
    cudaFuncSetAttribute(k_gemm_mma, cudaFuncAttributeMaxDynamicSharedMemorySize, SMEM_GEMM);

    k_init<<<(NN + 255) / 256, 256>>>();
    k_cvt<<<(N4 + 255) / 256, 256>>>(x);
    k_hist<<<(NE + 255) / 256, 256>>>(edst);
    k_scan1<<<SCAN_BLK, 1024>>>();
    k_scan2<<<1, 128>>>();
    k_scan3<<<SCAN_BLK, 1024>>>();
    k_scatter<<<(NE + 255) / 256, 256>>>(esrc, edst);
    k_gstartk<<<(NN + 255) / 256, 256>>>(gid);

    const int AGG_BLOCKS = (NN * 32 + 255) / 256;   // 12500
    const int ROW_TILES = (NN + 63) / 64;           // 1563
    dim3 gemm_grid(ROW_TILES, 2);

    // device pointers into device globals
    float4* Tl[4];
    cudaGetSymbolAddress((void**)&Tl[0], g_T);
    Tl[1] = Tl[0] + N4;
    Tl[2] = Tl[0] + 2 * N4;
    Tl[3] = Tl[0] + 3 * N4;
    uint2* Tbl[4];
    cudaGetSymbolAddress((void**)&Tbl[0], g_Tb);
    Tbl[1] = Tbl[0] + N4;
    Tbl[2] = Tbl[0] + 2 * N4;
    Tbl[3] = Tbl[0] + 3 * N4;
    uint2* xb; cudaGetSymbolAddress((void**)&xb, g_xb);
    float4* Pp; cudaGetSymbolAddress((void**)&Pp, g_P);
    float4* Zp; cudaGetSymbolAddress((void**)&Zp, g_Z);
    float* scL; cudaGetSymbolAddress((void**)&scL, g_scaleL);
    float* shL; cudaGetSymbolAddress((void**)&shL, g_shiftL);

    for (int l = 0; l < 4; ++l) {
        const uint2* src = (l == 0) ? (const uint2*)xb : (const uint2*)Tbl[l - 1];
        k_agg<<<AGG_BLOCKS, 256>>>(src, eps, l,
                                   scL + (l > 0 ? (l - 1) * DD : 0),
                                   shL + (l > 0 ? (l - 1) * DD : 0));
        k_gemm_mma<<<gemm_grid, 256, SMEM_GEMM>>>(Pp, (float*)Zp, nullptr,
                                                  W1 + l * 16384, b1 + l * 128, 0, NN);
        k_finalize<<<1, 128>>>(g1 + l * 128, bt1 + l * 128, -1);
        k_gemm_mma<<<gemm_grid, 256, SMEM_GEMM>>>(Zp, (float*)Tl[l], (uint32_t*)Tbl[l],
                                                  W2 + l * 16384, b2 + l * 128, 1, NN);
        k_finalize<<<1, 128>>>(g2 + l * 128, bt2 + l * 128, l);
    }
    k_fusepool<<<NG, 512>>>(fw);
    k_out<<<NG, 32>>>(Wp, bp, out);
}

// round 17
// speedup vs baseline: 1.0858x; 1.0582x over previous
#include <cuda_runtime.h>
#include <cuda_bf16.h>
#include <cstdint>

#define NN 100000
#define NE 1600000
#define NG 256
#define DD 128
#define N4 (NN * 32)   // float4 elements per node-feature matrix
#define SCAN_BLK 98    // 98 * 1024 >= NN

// ---------------- scratch (device globals: allocation-free) ----------------
__device__ float4 g_P[N4];       // pooled (agg output, pre-GEMM1)
__device__ float4 g_Z[N4];       // GEMM1 output (pre-BN1)
__device__ float4 g_T[4][N4];    // per-layer GEMM2 output (pre-BN2)
__device__ int    g_counts[NN];
__device__ int    g_rowptr[NN + 1];
__device__ int    g_cursor[NN];
__device__ int    g_csr[NE];
__device__ int    g_bsum[SCAN_BLK];
__device__ int    g_boff[SCAN_BLK];
__device__ float  g_sum[DD];
__device__ float  g_sq[DD];
__device__ float  g_scale[DD];     // current BN (BN1 for gemm2 A-load)
__device__ float  g_shift[DD];
__device__ float  g_scaleL[4][DD]; // saved BN2 per layer
__device__ float  g_shiftL[4][DD];
__device__ int    g_gstart[NG + 1];

__device__ __forceinline__ uint32_t f2tf32(float v) {
    uint32_t u;
    asm("cvt.rna.tf32.f32 %0, %1;" : "=r"(u) : "f"(v));
    return u;
}
__device__ __forceinline__ void mma_tf32(float* d, const uint32_t* a, const uint32_t* b) {
    asm volatile("mma.sync.aligned.m16n8k8.row.col.f32.tf32.tf32.f32 "
        "{%0,%1,%2,%3}, {%4,%5,%6,%7}, {%8,%9}, {%0,%1,%2,%3};"
        : "+f"(d[0]), "+f"(d[1]), "+f"(d[2]), "+f"(d[3])
        : "r"(a[0]), "r"(a[1]), "r"(a[2]), "r"(a[3]), "r"(b[0]), "r"(b[1]));
}
__device__ __forceinline__ void fuse_acc(float4& acc, float4 t, float4 sc, float4 sh, float wl) {
    acc.x = fmaf(wl, fmaxf(fmaf(t.x, sc.x, sh.x), 0.0f), acc.x);
    acc.y = fmaf(wl, fmaxf(fmaf(t.y, sc.y, sh.y), 0.0f), acc.y);
    acc.z = fmaf(wl, fmaxf(fmaf(t.z, sc.z, sh.z), 0.0f), acc.z);
    acc.w = fmaf(wl, fmaxf(fmaf(t.w, sc.w, sh.w), 0.0f), acc.w);
}

// ---------------- init ----------------
__global__ void k_init() {
    int i = blockIdx.x * blockDim.x + threadIdx.x;
    if (i < NN) g_counts[i] = 0;
    if (i < DD) { g_sum[i] = 0.0f; g_sq[i] = 0.0f; }
}

// ---------------- CSR build ----------------
__global__ void k_hist(const int* __restrict__ dst) {
    cudaGridDependencySynchronize();
    int i = blockIdx.x * blockDim.x + threadIdx.x;
    if (i < NE) atomicAdd(&g_counts[dst[i]], 1);
}

__device__ __forceinline__ int block_scan_inc(int v, int* sm) {
    int t = threadIdx.x;
    int lane = t & 31;
    int w = t >> 5;
#pragma unroll
    for (int d = 1; d < 32; d <<= 1) {
        int n = __shfl_up_sync(0xffffffffu, v, d);
        if (lane >= d) v += n;
    }
    if (lane == 31) sm[w] = v;
    __syncthreads();
    if (w == 0) {
        int s = (lane < 32) ? sm[lane] : 0;
#pragma unroll
        for (int d = 1; d < 32; d <<= 1) {
            int n = __shfl_up_sync(0xffffffffu, s, d);
            if (lane >= d) s += n;
        }
        sm[lane] = s;
    }
    __syncthreads();
    if (w > 0) v += sm[w - 1];
    return v;
}

__global__ void k_scan1() {
    cudaGridDependencySynchronize();
    __shared__ int sm[32];
    int idx = blockIdx.x * 1024 + threadIdx.x;
    int v = (idx < NN) ? g_counts[idx] : 0;
    int inc = block_scan_inc(v, sm);
    if (threadIdx.x == 1023) g_bsum[blockIdx.x] = inc;
}

__global__ void k_scan2() {
    cudaGridDependencySynchronize();
    __shared__ int sm[32];
    int t = threadIdx.x;   // 128 threads
    int v = (t < SCAN_BLK) ? g_bsum[t] : 0;
    int lane = t & 31;
    int w = t >> 5;
#pragma unroll
    for (int d = 1; d < 32; d <<= 1) {
        int n = __shfl_up_sync(0xffffffffu, v, d);
        if (lane >= d) v += n;
    }
    if (lane == 31) sm[w] = v;
    __syncthreads();
    if (w == 0) {
        int s = (lane < 4) ? sm[lane] : 0;
#pragma unroll
        for (int d = 1; d < 4; d <<= 1) {
            int n = __shfl_up_sync(0xffffffffu, s, d);
            if (lane >= d) s += n;
        }
        sm[lane] = s;
    }
    __syncthreads();
    if (w > 0) v += sm[w - 1];
    if (t < SCAN_BLK) g_boff[t] = v - g_bsum[t];
    if (t == SCAN_BLK - 1) g_rowptr[NN] = v;
}

__global__ void k_scan3() {
    cudaGridDependencySynchronize();
    __shared__ int sm[32];
    int idx = blockIdx.x * 1024 + threadIdx.x;
    int v = (idx < NN) ? g_counts[idx] : 0;
    int inc = block_scan_inc(v, sm);
    int exc = inc - v + g_boff[blockIdx.x];
    if (idx < NN) {
        g_rowptr[idx] = exc;
        g_cursor[idx] = exc;
    }
}

// scatter + gstart merged (independent work, one launch)
__global__ void k_scatter(const int* __restrict__ src, const int* __restrict__ dst,
                          const int* __restrict__ gid) {
    cudaGridDependencySynchronize();
    int i = blockIdx.x * blockDim.x + threadIdx.x;
    if (i < NE) {
        int p = atomicAdd(&g_cursor[dst[i]], 1);
        g_csr[p] = src[i];
    }
    if (i < NN) {
        int cur = __ldg(&gid[i]);
        int prev = (i == 0) ? -1 : __ldg(&gid[i - 1]);
        for (int g = prev + 1; g <= cur; ++g) g_gstart[g] = i;
        if (i == NN - 1)
            for (int g = cur + 1; g <= NG; ++g) g_gstart[g] = NN;
    }
}

// ------- aggregation: pooled = (1+eps)*f(self) + sum f(neighbors), f = relu(BN) or id ------
__global__ void k_agg(const float4* __restrict__ src, const float* __restrict__ eps,
                      int layer, const float* __restrict__ scl, const float* __restrict__ shl) {
    int gt = blockIdx.x * blockDim.x + threadIdx.x;
    int node = gt >> 5;
    int lane = gt & 31;
    // pre-sync: CSR topology is ready long before the predecessor GEMM finishes
    int beg = 0, end = 0;
    if (node < NN) {
        beg = g_rowptr[node];
        end = g_rowptr[node + 1];
    }
    cudaGridDependencySynchronize();
    if (node >= NN) return;
    bool bn = layer > 0;
    float4 sc = make_float4(1.0f, 1.0f, 1.0f, 1.0f);
    float4 sh = make_float4(0.0f, 0.0f, 0.0f, 0.0f);
    if (bn) {
        sc = __ldg(&((const float4*)scl)[lane]);
        sh = __ldg(&((const float4*)shl)[lane]);
    }
    float ep = 1.0f + __ldg(&eps[layer]);

#define XF(v) do { if (bn) { \
        v.x = fmaxf(fmaf(v.x, sc.x, sh.x), 0.0f); \
        v.y = fmaxf(fmaf(v.y, sc.y, sh.y), 0.0f); \
        v.z = fmaxf(fmaf(v.z, sc.z, sh.z), 0.0f); \
        v.w = fmaxf(fmaf(v.w, sc.w, sh.w), 0.0f); } } while (0)

    float4 self = src[node * 32 + lane];
    XF(self);
    float4 acc;
    acc.x = ep * self.x; acc.y = ep * self.y; acc.z = ep * self.z; acc.w = ep * self.w;
    int e = beg;
    for (; e + 4 <= end; e += 4) {
        int s0 = __ldg(&g_csr[e]);
        int s1 = __ldg(&g_csr[e + 1]);
        int s2 = __ldg(&g_csr[e + 2]);
        int s3 = __ldg(&g_csr[e + 3]);
        float4 v0 = src[s0 * 32 + lane];
        float4 v1 = src[s1 * 32 + lane];
        float4 v2 = src[s2 * 32 + lane];
        float4 v3 = src[s3 * 32 + lane];
        XF(v0); XF(v1); XF(v2); XF(v3);
        acc.x += (v0.x + v1.x) + (v2.x + v3.x);
        acc.y += (v0.y + v1.y) + (v2.y + v3.y);
        acc.z += (v0.z + v1.z) + (v2.z + v3.z);
        acc.w += (v0.w + v1.w) + (v2.w + v3.w);
    }
    for (; e < end; ++e) {
        int s = __ldg(&g_csr[e]);
        float4 v = src[s * 32 + lane];
        XF(v);
        acc.x += v.x; acc.y += v.y; acc.z += v.z; acc.w += v.w;
    }
    g_P[node * 32 + lane] = acc;
#undef XF
}

// ---------- tf32 mma.sync GEMM: 64x64x128 tile/CTA (3 CTA/SM), fused bias + BN stats -----
// grid (rowTiles, 2): blockIdx.y selects the 64-column half of W.
// mode 0: A raw; mode 1: A = relu(BN(A)) on the fly (g_scale/g_shift)
#define LDA 132
#define LDW2 72
#define AS_U32 (64 * LDA)           // 8448
#define WK2_U32 (128 * LDW2)        // 9216
__global__ void __launch_bounds__(256, 3)
k_gemm_mma(const float4* __restrict__ A, float* __restrict__ Yf,
           const float* __restrict__ W, const float* __restrict__ bias, int mode, int M) {
    extern __shared__ uint32_t smem[];
    uint32_t* As = smem;                            // 8448 u32
    uint32_t* Wk = smem + AS_U32;                   // 9216 u32
    float* sS = (float*)(smem + AS_U32 + WK2_U32);  // 64
    float* sQ = sS + 64;                            // 64

    int tid = threadIdx.x;
    int lane = tid & 31;
    int wid = tid >> 5;
    int wm = wid & 1;       // warp row (2 x 32 rows)
    int wn = wid >> 1;      // warp col (4 x 16 cols)
    int gr = lane >> 2;     // group row 0..7
    int tg = lane & 3;      // thread-in-group 0..3

    int rowBase = blockIdx.x * 64;
    int nBase = blockIdx.y * 64;

    if (tid < 64) { sS[tid] = 0.0f; sQ[tid] = 0.0f; }

    // pre-sync: stage W half (kernel input, independent of predecessor output)
    {
        const float4* W4 = (const float4*)W;
        int nb4 = nBase >> 2;
        for (int j = tid; j < 2048; j += 256) {
            int k = j >> 4;
            int n4 = j & 15;
            float4 w = __ldg(&W4[k * 32 + nb4 + n4]);
            uint4 u;
            u.x = f2tf32(w.x); u.y = f2tf32(w.y); u.z = f2tf32(w.z); u.w = f2tf32(w.w);
            *(uint4*)&Wk[k * LDW2 + n4 * 4] = u;
        }
    }
    cudaGridDependencySynchronize();

    const float4* sc4 = (const float4*)g_scale;
    const float4* sh4 = (const float4*)g_shift;

    // stage A tile (64 rows), tf32-converted, optional BN+ReLU
    for (int j = tid; j < 2048; j += 256) {
        int r = j >> 5;
        int q = j & 31;
        int row = rowBase + r;
        float4 v = make_float4(0.0f, 0.0f, 0.0f, 0.0f);
        if (row < M) {
            v = A[row * 32 + q];
            if (mode) {
                float4 sc = sc4[q];
                float4 sh = sh4[q];
                v.x = fmaxf(fmaf(v.x, sc.x, sh.x), 0.0f);
                v.y = fmaxf(fmaf(v.y, sc.y, sh.y), 0.0f);
                v.z = fmaxf(fmaf(v.z, sc.z, sh.z), 0.0f);
                v.w = fmaxf(fmaf(v.w, sc.w, sh.w), 0.0f);
            }
        }
        uint4 u;
        u.x = f2tf32(v.x); u.y = f2tf32(v.y); u.z = f2tf32(v.z); u.w = f2tf32(v.w);
        *(uint4*)&As[r * LDA + q * 4] = u;
    }
    __syncthreads();

    // mainloop: warp tile 32 (m) x 16 (n)
    float C[2][2][4];
#pragma unroll
    for (int m = 0; m < 2; ++m)
#pragma unroll
        for (int t = 0; t < 2; ++t)
#pragma unroll
            for (int c = 0; c < 4; ++c) C[m][t][c] = 0.0f;

    const uint32_t* Asw = As + (wm * 32 + gr) * LDA + tg;
    const uint32_t* Wkw = Wk + tg * LDW2 + (wn * 16 + gr);

#pragma unroll
    for (int ks = 0; ks < 128; ks += 8) {
        uint32_t a[2][4];
#pragma unroll
        for (int m = 0; m < 2; ++m) {
            const uint32_t* p = Asw + m * 16 * LDA + ks;
            a[m][0] = p[0];
            a[m][1] = p[8 * LDA];
            a[m][2] = p[4];
            a[m][3] = p[8 * LDA + 4];
        }
        const uint32_t* qb = Wkw + ks * LDW2;
#pragma unroll
        for (int t = 0; t < 2; ++t) {
            uint32_t b[2];
            b[0] = qb[t * 8];
            b[1] = qb[4 * LDW2 + t * 8];
            mma_tf32(C[0][t], a[0], b);
            mma_tf32(C[1][t], a[1], b);
        }
    }

    // epilogue: bias, store, per-column sum/sumsq (local 64-col stats)
#pragma unroll
    for (int t = 0; t < 2; ++t) {
        int colL = wn * 16 + t * 8 + tg * 2;
        int col0 = nBase + colL;
        float b0 = __ldg(&bias[col0]);
        float b1 = __ldg(&bias[col0 + 1]);
        float s0 = 0.0f, s1 = 0.0f, q0 = 0.0f, q1 = 0.0f;
#pragma unroll
        for (int m = 0; m < 2; ++m) {
            int r0 = rowBase + wm * 32 + m * 16 + gr;
            if (r0 < M) {
                float o0 = C[m][t][0] + b0;
                float o1 = C[m][t][1] + b1;
                *(float2*)&Yf[r0 * 128 + col0] = make_float2(o0, o1);
                s0 += o0; q0 += o0 * o0;
                s1 += o1; q1 += o1 * o1;
            }
            int r1 = r0 + 8;
            if (r1 < M) {
                float o2 = C[m][t][2] + b0;
                float o3 = C[m][t][3] + b1;
                *(float2*)&Yf[r1 * 128 + col0] = make_float2(o2, o3);
                s0 += o2; q0 += o2 * o2;
                s1 += o3; q1 += o3 * o3;
            }
        }
#pragma unroll
        for (int d = 4; d < 32; d <<= 1) {
            s0 += __shfl_xor_sync(0xffffffffu, s0, d);
            s1 += __shfl_xor_sync(0xffffffffu, s1, d);
            q0 += __shfl_xor_sync(0xffffffffu, q0, d);
            q1 += __shfl_xor_sync(0xffffffffu, q1, d);
        }
        if (gr == 0) {
            atomicAdd(&sS[colL], s0);
            atomicAdd(&sS[colL + 1], s1);
            atomicAdd(&sQ[colL], q0);
            atomicAdd(&sQ[colL + 1], q1);
        }
    }
    __syncthreads();
    if (tid < 64) {
        atomicAdd(&g_sum[nBase + tid], sS[tid]);
        atomicAdd(&g_sq[nBase + tid], sQ[tid]);
    }
}

// ---------------- BN finalize: (sum,sumsq)->(scale,shift), save per-layer, reset ----------
__global__ void k_finalize(const float* __restrict__ gamma, const float* __restrict__ beta,
                           int slot) {
    cudaGridDependencySynchronize();
    int t = threadIdx.x;
    float m = g_sum[t] * (1.0f / NN);
    float q = g_sq[t] * (1.0f / NN);
    float var = q - m * m;
    float rstd = rsqrtf(var + 1e-5f);
    float sc = rstd * __ldg(&gamma[t]);
    float sh = fmaf(-m, sc, __ldg(&beta[t]));
    g_scale[t] = sc;
    g_shift[t] = sh;
    if (slot >= 0) { g_scaleL[slot][t] = sc; g_shiftL[slot][t] = sh; }
    g_sum[t] = 0.0f;
    g_sq[t] = 0.0f;
}

// --- fuse+pool+out: per graph, pool sum_l w_l*relu(BN_l(T_l)); then 128->10 linear -------
__global__ void __launch_bounds__(512)
k_fusepool(const float* __restrict__ fw, const float* __restrict__ Wp,
           const float* __restrict__ bp, float* __restrict__ out) {
    __shared__ float4 red[512];
    int g = blockIdx.x;
    int tid = threadIdx.x;
    int c4 = tid & 31;
    int sr = tid >> 5;   // 16 subrows
    cudaGridDependencySynchronize();
    float w0 = __ldg(&fw[0]), w1 = __ldg(&fw[1]), w2 = __ldg(&fw[2]), w3 = __ldg(&fw[3]);
    float4 sc0 = __ldg(&((const float4*)g_scaleL[0])[c4]);
    float4 sh0 = __ldg(&((const float4*)g_shiftL[0])[c4]);
    float4 sc1 = __ldg(&((const float4*)g_scaleL[1])[c4]);
    float4 sh1 = __ldg(&((const float4*)g_shiftL[1])[c4]);
    float4 sc2 = __ldg(&((const float4*)g_scaleL[2])[c4]);
    float4 sh2 = __ldg(&((const float4*)g_shiftL[2])[c4]);
    float4 sc3 = __ldg(&((const float4*)g_scaleL[3])[c4]);
    float4 sh3 = __ldg(&((const float4*)g_shiftL[3])[c4]);
    float4 acc = make_float4(0.0f, 0.0f, 0.0f, 0.0f);
    int beg = g_gstart[g];
    int end = g_gstart[g + 1];
    for (int n = beg + sr; n < end; n += 16) {
        int idx = n * 32 + c4;
        fuse_acc(acc, g_T[0][idx], sc0, sh0, w0);
        fuse_acc(acc, g_T[1][idx], sc1, sh1, w1);
        fuse_acc(acc, g_T[2][idx], sc2, sh2, w2);
        fuse_acc(acc, g_T[3][idx], sc3, sh3, w3);
    }
    red[tid] = acc;
    __syncthreads();
    if (sr < 4) {
        float4 a = red[sr * 32 + c4];
#pragma unroll
        for (int s = 4; s < 16; s += 4) {
            float4 b = red[(sr + s) * 32 + c4];
            a.x += b.x; a.y += b.y; a.z += b.z; a.w += b.w;
        }
        red[sr * 32 + c4] = a;
    }
    __syncthreads();
    if (sr == 0) {
        float4 a = red[c4];
#pragma unroll
        for (int s = 1; s < 4; ++s) {
            float4 b = red[s * 32 + c4];
            a.x += b.x; a.y += b.y; a.z += b.z; a.w += b.w;
        }
        red[c4] = a;    // pooled vector for graph g now in red[0..31] (128 floats)
        __syncwarp();
        // final linear 128 -> 10 within warp 0
        const float* pooled = (const float*)red;
        float accj[10];
#pragma unroll
        for (int j = 0; j < 10; ++j) accj[j] = 0.0f;
        for (int k = c4; k < DD; k += 32) {
            float pv = pooled[k];
#pragma unroll
            for (int j = 0; j < 10; ++j) accj[j] += pv * __ldg(&Wp[k * 10 + j]);
        }
#pragma unroll
        for (int j = 0; j < 10; ++j) {
            float v = accj[j];
            v += __shfl_xor_sync(0xffffffffu, v, 16);
            v += __shfl_xor_sync(0xffffffffu, v, 8);
            v += __shfl_xor_sync(0xffffffffu, v, 4);
            v += __shfl_xor_sync(0xffffffffu, v, 2);
            v += __shfl_xor_sync(0xffffffffu, v, 1);
            if (c4 == 0) out[g * 10 + j] = v + __ldg(&bp[j]);
        }
    }
}

// ---------------- PDL launch helper ----------------
template <typename K, typename... Args>
static void pdl(K kernel, dim3 grid, dim3 block, size_t smem, Args... args) {
    cudaLaunchConfig_t cfg = {};
    cfg.gridDim = grid;
    cfg.blockDim = block;
    cfg.dynamicSmemBytes = smem;
    cudaLaunchAttribute attr[1];
    attr[0].id = cudaLaunchAttributeProgrammaticStreamSerialization;
    attr[0].val.programmaticStreamSerializationAllowed = 1;
    cfg.attrs = attr;
    cfg.numAttrs = 1;
    cudaLaunchKernelEx(&cfg, kernel, args...);
}

// ---------------- launch ----------------
extern "C" void kernel_launch(void* const* d_in, const int* in_sizes, int n_in,
                              void* d_out, int out_size) {
    const float4* x   = (const float4*)d_in[0];
    const int* esrc   = (const int*)d_in[1];
    const int* edst   = (const int*)d_in[2];
    const int* gid    = (const int*)d_in[3];
    const float* eps  = (const float*)d_in[4];
    const float* fw   = (const float*)d_in[5];
    const float* W1   = (const float*)d_in[6];
    const float* b1   = (const float*)d_in[7];
    const float* g1   = (const float*)d_in[8];
    const float* bt1  = (const float*)d_in[9];
    const float* W2   = (const float*)d_in[10];
    const float* b2   = (const float*)d_in[11];
    const float* g2   = (const float*)d_in[12];
    const float* bt2  = (const float*)d_in[13];
    const float* Wp   = (const float*)d_in[14];
    const float* bp   = (const float*)d_in[15];
    float* out        = (float*)d_out;

    const int SMEM_GEMM = (AS_U32 + WK2_U32 + 128) * 4;   // 71168 bytes -> 3 CTA/SM
    cudaFuncSetAttribute(k_gemm_mma, cudaFuncAttributeMaxDynamicSharedMemorySize, SMEM_GEMM);

    k_init<<<(NN + 255) / 256, 256>>>();
    pdl(k_hist, dim3((NE + 255) / 256), dim3(256), 0, edst);
    pdl(k_scan1, dim3(SCAN_BLK), dim3(1024), 0);
    pdl(k_scan2, dim3(1), dim3(128), 0);
    pdl(k_scan3, dim3(SCAN_BLK), dim3(1024), 0);
    pdl(k_scatter, dim3((NE + 255) / 256), dim3(256), 0, esrc, edst, gid);

    const int AGG_BLOCKS = (NN * 32 + 255) / 256;   // 12500
    const int ROW_TILES = (NN + 63) / 64;           // 1563
    dim3 gemm_grid(ROW_TILES, 2);

    // device pointers into device globals
    float4* Tl[4];
    cudaGetSymbolAddress((void**)&Tl[0], g_T);
    Tl[1] = Tl[0] + N4;
    Tl[2] = Tl[0] + 2 * N4;
    Tl[3] = Tl[0] + 3 * N4;
    float4* Pp; cudaGetSymbolAddress((void**)&Pp, g_P);
    float4* Zp; cudaGetSymbolAddress((void**)&Zp, g_Z);
    float* scL; cudaGetSymbolAddress((void**)&scL, g_scaleL);
    float* shL; cudaGetSymbolAddress((void**)&shL, g_shiftL);

    for (int l = 0; l < 4; ++l) {
        const float4* src = (l == 0) ? x : (const float4*)Tl[l - 1];
        pdl(k_agg, dim3(AGG_BLOCKS), dim3(256), 0, src, eps, l,
            (const float*)(scL + (l > 0 ? (l - 1) * DD : 0)),
            (const float*)(shL + (l > 0 ? (l - 1) * DD : 0)));
        pdl(k_gemm_mma, gemm_grid, dim3(256), (size_t)SMEM_GEMM,
            (const float4*)Pp, (float*)Zp, W1 + l * 16384, b1 + l * 128, 0, NN);
        pdl(k_finalize, dim3(1), dim3(128), 0, g1 + l * 128, bt1 + l * 128, -1);
        pdl(k_gemm_mma, gemm_grid, dim3(256), (size_t)SMEM_GEMM,
            (const float4*)Zp, (float*)Tl[l], W2 + l * 16384, b2 + l * 128, 1, NN);
        pdl(k_finalize, dim3(1), dim3(128), 0, g2 + l * 128, bt2 + l * 128, l);
    }
    pdl(k_fusepool, dim3(NG), dim3(512), 0, fw, Wp, bp, out);
}